// round 1
// baseline (speedup 1.0000x reference)
#include <cuda_runtime.h>

#define N_NODES 50000
#define N_EDGES 400000
#define EMB 384
#define EMB2 768
#define NLAYER 5
#define NUM_GRAPHS 128
#define BN_EPS 1e-5f
#define GOFF (NUM_GRAPHS * EMB)   // offset of h in d_out

// ---------------- scratch (device globals; no allocation allowed) ----------
__device__ float g_h [N_NODES * EMB];     // node features between layers
__device__ float g_e [N_EDGES * EMB];     // edge features (fixed across layers)
__device__ float g_z1[N_NODES * EMB];     // z after aggregation / z3 after GEMM2
__device__ float g_z2[N_NODES * EMB2];    // z after GEMM1
__device__ int   g_deg[N_NODES];
__device__ int   g_rowptr[N_NODES + 1];
__device__ int   g_cursor[N_NODES];
__device__ int   g_csr_src[N_EDGES];
__device__ int   g_csr_eid[N_EDGES];
__device__ float g_sum[EMB2];
__device__ float g_sumsq[EMB2];
__device__ float g_scale[EMB2];
__device__ float g_shift[EMB2];
__device__ int   g_gstart[NUM_GRAPHS + 1];

// ---------------- encoders -------------------------------------------------
__global__ void encode_nodes(const int* __restrict__ x,
                             const float* __restrict__ atom_emb) {
    int n = blockIdx.x;          // 50000 blocks, 384 threads
    int c = threadIdx.x;
    __shared__ int xs[9];
    if (c < 9) xs[c] = x[n * 9 + c];
    __syncthreads();
    float s = 0.f;
#pragma unroll
    for (int k = 0; k < 9; k++)
        s += atom_emb[((k << 6) + xs[k]) * EMB + c];
    g_h[(size_t)n * EMB + c] = s;
}

__global__ void encode_edges(const int* __restrict__ ea,
                             const float* __restrict__ bond_emb) {
    int e = blockIdx.x;          // 400000 blocks, 384 threads
    int c = threadIdx.x;
    __shared__ int es[3];
    if (c < 3) es[c] = ea[e * 3 + c];
    __syncthreads();
    float s = 0.f;
#pragma unroll
    for (int k = 0; k < 3; k++)
        s += bond_emb[((k << 3) + es[k]) * EMB + c];
    g_e[(size_t)e * EMB + c] = s;
}

// ---------------- CSR build ------------------------------------------------
__global__ void zero_deg() {
    int i = blockIdx.x * blockDim.x + threadIdx.x;
    if (i < N_NODES) g_deg[i] = 0;
}

__global__ void count_deg(const int* __restrict__ ei) {
    int e = blockIdx.x * blockDim.x + threadIdx.x;
    if (e < N_EDGES) atomicAdd(&g_deg[ei[N_EDGES + e]], 1);
}

__global__ void scan_deg() {   // 1 block, 1024 threads
    __shared__ int part[1024];
    const int T = 1024;
    int tid = threadIdx.x;
    const int per = (N_NODES + T - 1) / T;   // 49
    int start = tid * per;
    int end   = start + per; if (end > N_NODES) end = N_NODES;
    if (start > N_NODES) start = N_NODES;
    int s = 0;
    for (int i = start; i < end; i++) s += g_deg[i];
    part[tid] = s;
    __syncthreads();
    for (int off = 1; off < T; off <<= 1) {
        int v = (tid >= off) ? part[tid - off] : 0;
        __syncthreads();
        part[tid] += v;
        __syncthreads();
    }
    int run = (tid == 0) ? 0 : part[tid - 1];
    for (int i = start; i < end; i++) {
        g_rowptr[i] = run;
        g_cursor[i] = run;
        run += g_deg[i];
    }
    if (tid == T - 1) g_rowptr[N_NODES] = run;
}

__global__ void fill_csr(const int* __restrict__ ei) {
    int e = blockIdx.x * blockDim.x + threadIdx.x;
    if (e >= N_EDGES) return;
    int dst = ei[N_EDGES + e];
    int pos = atomicAdd(&g_cursor[dst], 1);
    g_csr_src[pos] = ei[e];
    g_csr_eid[pos] = e;
}

// ---------------- GINE aggregation: z1 = h + sum_in relu(h[src]+e) ---------
__global__ void aggregate() {
    int n = blockIdx.x;          // 50000 blocks, 128 threads (3 cols each)
    int t = threadIdx.x;
    const float* hr0 = g_h + (size_t)n * EMB;
    float a0 = hr0[t], a1 = hr0[t + 128], a2 = hr0[t + 256];
    int p0 = g_rowptr[n], p1 = g_rowptr[n + 1];
    for (int p = p0; p < p1; p++) {
        int s  = g_csr_src[p];
        int id = g_csr_eid[p];
        const float* hs = g_h + (size_t)s * EMB;
        const float* er = g_e + (size_t)id * EMB;
        a0 += fmaxf(hs[t]       + er[t],       0.f);
        a1 += fmaxf(hs[t + 128] + er[t + 128], 0.f);
        a2 += fmaxf(hs[t + 256] + er[t + 256], 0.f);
    }
    float* z = g_z1 + (size_t)n * EMB;
    z[t] = a0; z[t + 128] = a1; z[t + 256] = a2;
}

// ---------------- SGEMM: C = A @ B + bias  (A MxK, B KxN row-major) --------
__global__ __launch_bounds__(256)
void sgemm_bias(const float* __restrict__ A, const float* __restrict__ B,
                const float* __restrict__ bias, float* __restrict__ C,
                int M, int N, int K) {
    const int BM = 128, BN = 128, BK = 16, TM = 8, TN = 8;
    __shared__ float As[BK][BM];
    __shared__ float Bs[BK][BN];
    int tid  = threadIdx.x;
    int tr   = tid / 16;         // 0..15
    int tc   = tid % 16;         // 0..15
    int row0 = blockIdx.y * BM;
    int col0 = blockIdx.x * BN;

    int a_row  = tid / 4;        // 0..63 (two rows: +0, +64)
    int a_col4 = tid % 4;        // float4 index within BK
    int b_row  = tid / 32;       // 0..7 (two rows: +0, +8)
    int b_col4 = tid % 32;       // float4 col index

    float acc[TM][TN];
#pragma unroll
    for (int i = 0; i < TM; i++)
#pragma unroll
        for (int j = 0; j < TN; j++) acc[i][j] = 0.f;

    for (int k0 = 0; k0 < K; k0 += BK) {
#pragma unroll
        for (int i = 0; i < 2; i++) {
            int r  = a_row + i * 64;
            int gr = row0 + r;
            float4 v = (gr < M)
                ? *(const float4*)&A[(size_t)gr * K + k0 + a_col4 * 4]
                : make_float4(0.f, 0.f, 0.f, 0.f);
            As[a_col4 * 4 + 0][r] = v.x;
            As[a_col4 * 4 + 1][r] = v.y;
            As[a_col4 * 4 + 2][r] = v.z;
            As[a_col4 * 4 + 3][r] = v.w;
        }
#pragma unroll
        for (int i = 0; i < 2; i++) {
            int r = b_row + i * 8;
            *(float4*)&Bs[r][b_col4 * 4] =
                *(const float4*)&B[(size_t)(k0 + r) * N + col0 + b_col4 * 4];
        }
        __syncthreads();
#pragma unroll
        for (int k = 0; k < BK; k++) {
            float a[TM], b[TN];
            float4 av0 = *(const float4*)&As[k][tr * TM];
            float4 av1 = *(const float4*)&As[k][tr * TM + 4];
            a[0]=av0.x; a[1]=av0.y; a[2]=av0.z; a[3]=av0.w;
            a[4]=av1.x; a[5]=av1.y; a[6]=av1.z; a[7]=av1.w;
            float4 bv0 = *(const float4*)&Bs[k][tc * TN];
            float4 bv1 = *(const float4*)&Bs[k][tc * TN + 4];
            b[0]=bv0.x; b[1]=bv0.y; b[2]=bv0.z; b[3]=bv0.w;
            b[4]=bv1.x; b[5]=bv1.y; b[6]=bv1.z; b[7]=bv1.w;
#pragma unroll
            for (int i = 0; i < TM; i++)
#pragma unroll
                for (int j = 0; j < TN; j++)
                    acc[i][j] = fmaf(a[i], b[j], acc[i][j]);
        }
        __syncthreads();
    }
#pragma unroll
    for (int i = 0; i < TM; i++) {
        int r = row0 + tr * TM + i;
        if (r >= M) continue;
#pragma unroll
        for (int j = 0; j < TN; j += 4) {
            int c = col0 + tc * TN + j;
            float4 o;
            o.x = acc[i][j]     + bias[c];
            o.y = acc[i][j + 1] + bias[c + 1];
            o.z = acc[i][j + 2] + bias[c + 2];
            o.w = acc[i][j + 3] + bias[c + 3];
            *(float4*)&C[(size_t)r * N + c] = o;
        }
    }
}

// ---------------- BatchNorm (training mode) ---------------------------------
__global__ void zero_stats() {
    int c = blockIdx.x * blockDim.x + threadIdx.x;
    if (c < EMB2) { g_sum[c] = 0.f; g_sumsq[c] = 0.f; }
}

__global__ void colstats(const float* __restrict__ Z, int C, int rows_per_block) {
    int col = blockIdx.x * blockDim.x + threadIdx.x;   // blockDim 128
    int r0  = blockIdx.y * rows_per_block;
    int r1  = r0 + rows_per_block; if (r1 > N_NODES) r1 = N_NODES;
    float s = 0.f, q = 0.f;
    for (int r = r0; r < r1; r++) {
        float v = Z[(size_t)r * C + col];
        s += v; q += v * v;
    }
    atomicAdd(&g_sum[col], s);
    atomicAdd(&g_sumsq[col], q);
}

__global__ void bn_finalize(const float* __restrict__ gamma,
                            const float* __restrict__ beta, int C) {
    int c = blockIdx.x * blockDim.x + threadIdx.x;
    if (c >= C) return;
    float m   = g_sum[c] * (1.f / N_NODES);
    float v   = g_sumsq[c] * (1.f / N_NODES) - m * m;
    float inv = rsqrtf(v + BN_EPS);
    float sc  = gamma[c] * inv;
    g_scale[c] = sc;
    g_shift[c] = beta[c] - sc * m;
}

// y = relu(scale*z + shift); optional mirrored write (final layer -> d_out)
__global__ void bnrelu(const float* __restrict__ Z, float* __restrict__ O1,
                       float* __restrict__ O2) {
    int c = threadIdx.x;                 // blockDim == C
    size_t i = (size_t)blockIdx.x * blockDim.x + c;
    float v = fmaxf(g_scale[c] * Z[i] + g_shift[c], 0.f);
    O1[i] = v;
    if (O2) O2[i] = v;
}

// ---------------- pooling ---------------------------------------------------
__global__ void boundaries_kernel(const int* __restrict__ batch) {
    int g = threadIdx.x;   // 1 block, 128 threads
    if (g < NUM_GRAPHS) {
        int lo = 0, hi = N_NODES;
        while (lo < hi) {
            int mid = (lo + hi) >> 1;
            if (batch[mid] < g) lo = mid + 1; else hi = mid;
        }
        g_gstart[g] = lo;
    }
    if (g == 0) g_gstart[NUM_GRAPHS] = N_NODES;
}

__global__ void pool(const float* __restrict__ h, float* __restrict__ out) {
    int g = blockIdx.x;                  // 128 blocks, 128 threads
    int t = threadIdx.x;
    int s = g_gstart[g], e = g_gstart[g + 1];
    float a0 = 0.f, a1 = 0.f, a2 = 0.f;
    for (int r = s; r < e; r++) {
        const float* hr = h + (size_t)r * EMB;
        a0 += hr[t]; a1 += hr[t + 128]; a2 += hr[t + 256];
    }
    float* o = out + (size_t)g * EMB;
    o[t] = a0; o[t + 128] = a1; o[t + 256] = a2;
}

// ---------------- launch ----------------------------------------------------
extern "C" void kernel_launch(void* const* d_in, const int* in_sizes, int n_in,
                              void* d_out, int out_size) {
    const int*   batch    = (const int*)d_in[0];
    const int*   x        = (const int*)d_in[1];
    const int*   ei       = (const int*)d_in[2];
    const int*   ea       = (const int*)d_in[3];
    const float* atom_emb = (const float*)d_in[4];
    const float* bond_emb = (const float*)d_in[5];
    const float* W1       = (const float*)d_in[6];
    const float* b1       = (const float*)d_in[7];
    const float* g1       = (const float*)d_in[8];
    const float* be1      = (const float*)d_in[9];
    const float* W2       = (const float*)d_in[10];
    const float* b2       = (const float*)d_in[11];
    const float* gbn      = (const float*)d_in[12];
    const float* bbn      = (const float*)d_in[13];
    float* out = (float*)d_out;

    float* g_h_p;   cudaGetSymbolAddress((void**)&g_h_p,  g_h);
    float* g_z1_p;  cudaGetSymbolAddress((void**)&g_z1_p, g_z1);
    float* g_z2_p;  cudaGetSymbolAddress((void**)&g_z2_p, g_z2);

    // encoders
    encode_nodes<<<N_NODES, EMB>>>(x, atom_emb);
    encode_edges<<<N_EDGES, EMB>>>(ea, bond_emb);

    // CSR build (edge topology fixed across layers)
    zero_deg<<<(N_NODES + 255) / 256, 256>>>();
    count_deg<<<(N_EDGES + 255) / 256, 256>>>(ei);
    scan_deg<<<1, 1024>>>();
    fill_csr<<<(N_EDGES + 255) / 256, 256>>>(ei);

    const int GEMM_M_TILES = (N_NODES + 127) / 128;   // 391
    const int ROWCHUNK = 500;                         // 100 y-blocks for colstats

    for (int l = 0; l < NLAYER; l++) {
        // z1 = h + sum_in relu(h[src] + e)
        aggregate<<<N_NODES, 128>>>();

        // z2 = z1 @ W1[l] + b1[l]
        {
            dim3 grid(EMB2 / 128, GEMM_M_TILES);
            sgemm_bias<<<grid, 256>>>(g_z1_p, W1 + (size_t)l * EMB * EMB2,
                                      b1 + l * EMB2, g_z2_p,
                                      N_NODES, EMB2, EMB);
        }
        // BN1 stats + finalize, then z2 = relu(bn1(z2)) in place
        zero_stats<<<(EMB2 + 255) / 256, 256>>>();
        {
            dim3 grid(EMB2 / 128, (N_NODES + ROWCHUNK - 1) / ROWCHUNK);
            colstats<<<grid, 128>>>(g_z2_p, EMB2, ROWCHUNK);
        }
        bn_finalize<<<(EMB2 + 255) / 256, 256>>>(g1 + l * EMB2, be1 + l * EMB2, EMB2);
        bnrelu<<<N_NODES, EMB2>>>(g_z2_p, g_z2_p, nullptr);

        // z1 = z2 @ W2[l] + b2[l]
        {
            dim3 grid(EMB / 128, GEMM_M_TILES);
            sgemm_bias<<<grid, 256>>>(g_z2_p, W2 + (size_t)l * EMB2 * EMB,
                                      b2 + l * EMB, g_z1_p,
                                      N_NODES, EMB, EMB2);
        }
        // outer BN stats + finalize, then h = relu(bn(z1))
        zero_stats<<<(EMB2 + 255) / 256, 256>>>();
        {
            dim3 grid(EMB / 128, (N_NODES + ROWCHUNK - 1) / ROWCHUNK);
            colstats<<<grid, 128>>>(g_z1_p, EMB, ROWCHUNK);
        }
        bn_finalize<<<(EMB + 255) / 256, 256>>>(gbn + l * EMB, bbn + l * EMB, EMB);
        bnrelu<<<N_NODES, EMB>>>(g_z1_p, g_h_p,
                                 (l == NLAYER - 1) ? (out + GOFF) : nullptr);
    }

    // global add pool (batch is sorted)
    boundaries_kernel<<<1, 128>>>(batch);
    pool<<<NUM_GRAPHS, 128>>>(g_h_p, out);
}

// round 3
// speedup vs baseline: 1.4831x; 1.4831x over previous
#include <cuda_runtime.h>
#include <cuda_bf16.h>
#include <cstdint>

#define N_NODES 50000
#define N_EDGES 400000
#define EMB 384
#define EMB2 768
#define NLAYER 5
#define NUM_GRAPHS 128
#define BN_EPS 1e-5f
#define GOFF (NUM_GRAPHS * EMB)

// ---------------- scratch (device globals) ----------------------------------
__device__ float g_h [N_NODES * EMB];
__device__ float g_e [N_EDGES * EMB];
__device__ float g_z2[N_NODES * EMB2];   // GEMM1 output
__device__ float g_z1[N_NODES * EMB];    // GEMM2 output
__device__ __nv_bfloat16 g_Ahi[N_NODES * EMB2];
__device__ __nv_bfloat16 g_Alo[N_NODES * EMB2];
__device__ __nv_bfloat16 g_W1t_hi[NLAYER * EMB2 * EMB];
__device__ __nv_bfloat16 g_W1t_lo[NLAYER * EMB2 * EMB];
__device__ __nv_bfloat16 g_W2t_hi[NLAYER * EMB * EMB2];
__device__ __nv_bfloat16 g_W2t_lo[NLAYER * EMB * EMB2];
__device__ int   g_deg[N_NODES];
__device__ int   g_rowptr[N_NODES + 1];
__device__ int   g_cursor[N_NODES];
__device__ int   g_csr_src[N_EDGES];
__device__ int   g_csr_eid[N_EDGES];
__device__ float g_sum[EMB2];
__device__ float g_sumsq[EMB2];
__device__ float g_scale[EMB2];
__device__ float g_shift[EMB2];
__device__ int   g_gstart[NUM_GRAPHS + 1];

// ---------------- PTX helpers (sm_80-level only) -----------------------------
__device__ __forceinline__ uint32_t smem_u32(const void* p) {
    uint32_t a;
    asm("{ .reg .u64 t; cvta.to.shared.u64 t, %1; cvt.u32.u64 %0, t; }" : "=r"(a) : "l"(p));
    return a;
}
__device__ __forceinline__ void cp16(uint32_t dst, const void* src, int valid) {
    asm volatile("cp.async.ca.shared.global [%0], [%1], 16, %2;"
                 :: "r"(dst), "l"(src), "r"(valid ? 16 : 0));
}
__device__ __forceinline__ void cp_commit() {
    asm volatile("cp.async.commit_group;" ::: "memory");
}
__device__ __forceinline__ void cp_wait1() {
    asm volatile("cp.async.wait_group 1;" ::: "memory");
}
__device__ __forceinline__ void ldsm_x4(uint32_t& r0, uint32_t& r1, uint32_t& r2,
                                        uint32_t& r3, uint32_t addr) {
    asm volatile("ldmatrix.sync.aligned.m8n8.x4.shared.b16 {%0,%1,%2,%3}, [%4];"
                 : "=r"(r0), "=r"(r1), "=r"(r2), "=r"(r3) : "r"(addr));
}
__device__ __forceinline__ void mma16816(float* d, const uint32_t* a, const uint32_t* b) {
    asm volatile(
        "mma.sync.aligned.m16n8k16.row.col.f32.bf16.bf16.f32 "
        "{%0,%1,%2,%3}, {%4,%5,%6,%7}, {%8,%9}, {%0,%1,%2,%3};"
        : "+f"(d[0]), "+f"(d[1]), "+f"(d[2]), "+f"(d[3])
        : "r"(a[0]), "r"(a[1]), "r"(a[2]), "r"(a[3]), "r"(b[0]), "r"(b[1]));
}

// ---------------- encoders ---------------------------------------------------
__global__ void encode_nodes(const int* __restrict__ x,
                             const float* __restrict__ atom_emb) {
    int n = blockIdx.x, c = threadIdx.x;
    __shared__ int xs[9];
    if (c < 9) xs[c] = x[n * 9 + c];
    __syncthreads();
    float s = 0.f;
#pragma unroll
    for (int k = 0; k < 9; k++) s += atom_emb[((k << 6) + xs[k]) * EMB + c];
    g_h[(size_t)n * EMB + c] = s;
}

__global__ void encode_edges(const int* __restrict__ ea,
                             const float* __restrict__ bond_emb) {
    int e = blockIdx.x, c = threadIdx.x;
    __shared__ int es[3];
    if (c < 3) es[c] = ea[e * 3 + c];
    __syncthreads();
    float s = 0.f;
#pragma unroll
    for (int k = 0; k < 3; k++) s += bond_emb[((k << 3) + es[k]) * EMB + c];
    g_e[(size_t)e * EMB + c] = s;
}

// ---------------- CSR build --------------------------------------------------
__global__ void zero_deg() {
    int i = blockIdx.x * blockDim.x + threadIdx.x;
    if (i < N_NODES) g_deg[i] = 0;
}
__global__ void count_deg(const int* __restrict__ ei) {
    int e = blockIdx.x * blockDim.x + threadIdx.x;
    if (e < N_EDGES) atomicAdd(&g_deg[ei[N_EDGES + e]], 1);
}
__global__ void scan_deg() {
    __shared__ int part[1024];
    const int T = 1024;
    int tid = threadIdx.x;
    const int per = (N_NODES + T - 1) / T;
    int start = tid * per;
    int end = start + per; if (end > N_NODES) end = N_NODES;
    if (start > N_NODES) start = N_NODES;
    int s = 0;
    for (int i = start; i < end; i++) s += g_deg[i];
    part[tid] = s;
    __syncthreads();
    for (int off = 1; off < T; off <<= 1) {
        int v = (tid >= off) ? part[tid - off] : 0;
        __syncthreads();
        part[tid] += v;
        __syncthreads();
    }
    int run = (tid == 0) ? 0 : part[tid - 1];
    for (int i = start; i < end; i++) {
        g_rowptr[i] = run; g_cursor[i] = run; run += g_deg[i];
    }
    if (tid == T - 1) g_rowptr[N_NODES] = run;
}
__global__ void fill_csr(const int* __restrict__ ei) {
    int e = blockIdx.x * blockDim.x + threadIdx.x;
    if (e >= N_EDGES) return;
    int dst = ei[N_EDGES + e];
    int pos = atomicAdd(&g_cursor[dst], 1);
    g_csr_src[pos] = ei[e];
    g_csr_eid[pos] = e;
}

// ---------------- aggregation: out = split(h + sum relu(h[src]+e)) ----------
__global__ void aggregate() {
    int n = blockIdx.x, t = threadIdx.x;   // 128 threads, 3 cols each
    const float* hr0 = g_h + (size_t)n * EMB;
    float a0 = hr0[t], a1 = hr0[t + 128], a2 = hr0[t + 256];
    int p0 = g_rowptr[n], p1 = g_rowptr[n + 1];
    for (int p = p0; p < p1; p++) {
        int s = g_csr_src[p], id = g_csr_eid[p];
        const float* hs = g_h + (size_t)s * EMB;
        const float* er = g_e + (size_t)id * EMB;
        a0 += fmaxf(hs[t]       + er[t],       0.f);
        a1 += fmaxf(hs[t + 128] + er[t + 128], 0.f);
        a2 += fmaxf(hs[t + 256] + er[t + 256], 0.f);
    }
    size_t base = (size_t)n * EMB;
    float v[3] = {a0, a1, a2};
#pragma unroll
    for (int j = 0; j < 3; j++) {
        __nv_bfloat16 hi = __float2bfloat16(v[j]);
        g_Ahi[base + t + j * 128] = hi;
        g_Alo[base + t + j * 128] = __float2bfloat16(v[j] - __bfloat162float(hi));
    }
}

// ---------------- weight transpose + split (W[L][K][N] -> Wt[L][N][K]) ------
__global__ void wsplit(const float* __restrict__ W, __nv_bfloat16* __restrict__ Thi,
                       __nv_bfloat16* __restrict__ Tlo, int K, int N) {
    __shared__ float t[32][33];
    int l = blockIdx.z;
    int n0 = blockIdx.x * 32, k0 = blockIdx.y * 32;
    const float* Wl = W + (size_t)l * K * N;
    for (int i = threadIdx.y; i < 32; i += 8)
        t[i][threadIdx.x] = Wl[(size_t)(k0 + i) * N + n0 + threadIdx.x];
    __syncthreads();
    __nv_bfloat16* Hl = Thi + (size_t)l * K * N;
    __nv_bfloat16* Ll = Tlo + (size_t)l * K * N;
    for (int i = threadIdx.y; i < 32; i += 8) {
        float v = t[threadIdx.x][i];
        __nv_bfloat16 hi = __float2bfloat16(v);
        Hl[(size_t)(n0 + i) * K + k0 + threadIdx.x] = hi;
        Ll[(size_t)(n0 + i) * K + k0 + threadIdx.x] =
            __float2bfloat16(v - __bfloat162float(hi));
    }
}

// ---------------- HMMA bf16 split GEMM ---------------------------------------
// C[M,Ntot] = (Ahi+Alo)[M,K] @ (Whi+Wlo)[Ntot,K]^T + bias  (3-term split)
// 128x128 tile, 8 warps (64x32 each), BK=32, cp.async double buffer.
#define BK 32
#define LDS_E 40                      // padded row stride (elements)
#define TILE_B (128 * LDS_E * 2)      // bytes per A (or B) stage: 10240
__global__ __launch_bounds__(256)
void gemm_mma(const __nv_bfloat16* __restrict__ Ahi,
              const __nv_bfloat16* __restrict__ Alo,
              const __nv_bfloat16* __restrict__ Whi,
              const __nv_bfloat16* __restrict__ Wlo,
              const float* __restrict__ bias,
              float* __restrict__ C,
              int M, int Ntot, int K) {
    __shared__ __align__(16) char smem[4 * TILE_B];   // [stage][A|B]
    uint32_t sb = smem_u32(smem);
    const int CPS = K / BK;           // chunks per segment
    const int NC  = 3 * CPS;
    int tid = threadIdx.x, wid = tid >> 5, lane = tid & 31;
    int r0 = blockIdx.y * 128;
    int n0 = blockIdx.x * 128;
    int wm = (wid & 1) * 64;
    int wn = (wid >> 1) * 32;

    // cp.async mapping: 512 16B-chunks per operand per stage, 2 per thread
    int ldr  = tid >> 1;              // 0..127 row
    int ldc  = (tid & 1) * 2;         // chunk pair base (0 or 2)

    auto prefetch = [&](int c, int stage) {
        int seg = c / CPS;
        int kc = (c - seg * CPS) * BK;
        const __nv_bfloat16* Ap = (seg == 1) ? Alo : Ahi;
        const __nv_bfloat16* Bp = (seg == 2) ? Wlo : Whi;
        uint32_t abase = sb + stage * 2 * TILE_B;
        uint32_t bbase = abase + TILE_B;
        int ar = r0 + ldr;
        int av = ar < M;
        const __nv_bfloat16* asrc = Ap + (size_t)ar * K + kc + ldc * 8;
        uint32_t adst = abase + (ldr * LDS_E + ldc * 8) * 2;
        cp16(adst,      asrc,     av);
        cp16(adst + 16, asrc + 8, av);
        const __nv_bfloat16* bsrc = Bp + (size_t)(n0 + ldr) * K + kc + ldc * 8;
        uint32_t bdst = bbase + (ldr * LDS_E + ldc * 8) * 2;
        cp16(bdst,      bsrc,     1);
        cp16(bdst + 16, bsrc + 8, 1);
    };

    float acc[4][4][4];
#pragma unroll
    for (int i = 0; i < 4; i++)
#pragma unroll
        for (int j = 0; j < 4; j++)
#pragma unroll
            for (int q = 0; q < 4; q++) acc[i][j][q] = 0.f;

    prefetch(0, 0);
    cp_commit();

    for (int c = 0; c < NC; c++) {
        if (c + 1 < NC) prefetch(c + 1, (c + 1) & 1);
        cp_commit();
        cp_wait1();
        __syncthreads();

        uint32_t abase = sb + (c & 1) * 2 * TILE_B;
        uint32_t bbase = abase + TILE_B;
#pragma unroll
        for (int ks = 0; ks < 2; ks++) {
            int k0 = ks * 16;
            uint32_t af[4][4];
#pragma unroll
            for (int i = 0; i < 4; i++) {
                uint32_t addr = abase +
                    ((wm + i * 16 + (lane & 15)) * LDS_E + k0 + (lane >> 4) * 8) * 2;
                ldsm_x4(af[i][0], af[i][1], af[i][2], af[i][3], addr);
            }
            uint32_t bf[2][4];
#pragma unroll
            for (int p = 0; p < 2; p++) {
                uint32_t addr = bbase +
                    ((wn + p * 16 + (lane & 7) + ((lane >> 4) & 1) * 8) * LDS_E
                     + k0 + ((lane >> 3) & 1) * 8) * 2;
                ldsm_x4(bf[p][0], bf[p][1], bf[p][2], bf[p][3], addr);
            }
#pragma unroll
            for (int i = 0; i < 4; i++)
#pragma unroll
                for (int j = 0; j < 4; j++) {
                    uint32_t bb[2] = { bf[j >> 1][(j & 1) * 2],
                                       bf[j >> 1][(j & 1) * 2 + 1] };
                    mma16816(acc[i][j], af[i], bb);
                }
        }
        __syncthreads();
    }

    // epilogue: bias add, fp32 store
#pragma unroll
    for (int i = 0; i < 4; i++) {
        int ra = r0 + wm + i * 16 + (lane >> 2);
        int rb = ra + 8;
#pragma unroll
        for (int j = 0; j < 4; j++) {
            int col = n0 + wn + j * 8 + (lane & 3) * 2;
            float bx = bias[col], by = bias[col + 1];
            if (ra < M) {
                float2 o = make_float2(acc[i][j][0] + bx, acc[i][j][1] + by);
                *(float2*)(C + (size_t)ra * Ntot + col) = o;
            }
            if (rb < M) {
                float2 o = make_float2(acc[i][j][2] + bx, acc[i][j][3] + by);
                *(float2*)(C + (size_t)rb * Ntot + col) = o;
            }
        }
    }
}

// ---------------- BatchNorm (training mode) ----------------------------------
__global__ void zero_stats() {
    int c = blockIdx.x * blockDim.x + threadIdx.x;
    if (c < EMB2) { g_sum[c] = 0.f; g_sumsq[c] = 0.f; }
}
__global__ void colstats(const float* __restrict__ Z, int C, int rows_per_block) {
    int col = blockIdx.x * blockDim.x + threadIdx.x;
    int r0 = blockIdx.y * rows_per_block;
    int r1 = r0 + rows_per_block; if (r1 > N_NODES) r1 = N_NODES;
    float s = 0.f, q = 0.f;
    for (int r = r0; r < r1; r++) {
        float v = Z[(size_t)r * C + col];
        s += v; q += v * v;
    }
    atomicAdd(&g_sum[col], s);
    atomicAdd(&g_sumsq[col], q);
}
__global__ void bn_finalize(const float* __restrict__ gamma,
                            const float* __restrict__ beta, int C) {
    int c = blockIdx.x * blockDim.x + threadIdx.x;
    if (c >= C) return;
    float m = g_sum[c] * (1.f / N_NODES);
    float v = g_sumsq[c] * (1.f / N_NODES) - m * m;
    float inv = rsqrtf(v + BN_EPS);
    float sc = gamma[c] * inv;
    g_scale[c] = sc;
    g_shift[c] = beta[c] - sc * m;
}

__global__ void bnrelu_split(const float* __restrict__ Z,
                             __nv_bfloat16* __restrict__ Hi,
                             __nv_bfloat16* __restrict__ Lo) {
    int c = threadIdx.x;
    size_t i = (size_t)blockIdx.x * blockDim.x + c;
    float v = fmaxf(g_scale[c] * Z[i] + g_shift[c], 0.f);
    __nv_bfloat16 hi = __float2bfloat16(v);
    Hi[i] = hi;
    Lo[i] = __float2bfloat16(v - __bfloat162float(hi));
}

__global__ void bnrelu_out(const float* __restrict__ Z, float* __restrict__ O1,
                           float* __restrict__ O2) {
    int c = threadIdx.x;
    size_t i = (size_t)blockIdx.x * blockDim.x + c;
    float v = fmaxf(g_scale[c] * Z[i] + g_shift[c], 0.f);
    O1[i] = v;
    if (O2) O2[i] = v;
}

// ---------------- pooling -----------------------------------------------------
__global__ void boundaries_kernel(const int* __restrict__ batch) {
    int g = threadIdx.x;
    if (g < NUM_GRAPHS) {
        int lo = 0, hi = N_NODES;
        while (lo < hi) {
            int mid = (lo + hi) >> 1;
            if (batch[mid] < g) lo = mid + 1; else hi = mid;
        }
        g_gstart[g] = lo;
    }
    if (g == 0) g_gstart[NUM_GRAPHS] = N_NODES;
}
__global__ void pool(const float* __restrict__ h, float* __restrict__ out) {
    int g = blockIdx.x, t = threadIdx.x;
    int s = g_gstart[g], e = g_gstart[g + 1];
    float a0 = 0.f, a1 = 0.f, a2 = 0.f;
    for (int r = s; r < e; r++) {
        const float* hr = h + (size_t)r * EMB;
        a0 += hr[t]; a1 += hr[t + 128]; a2 += hr[t + 256];
    }
    float* o = out + (size_t)g * EMB;
    o[t] = a0; o[t + 128] = a1; o[t + 256] = a2;
}

// ---------------- launch --------------------------------------------------------
extern "C" void kernel_launch(void* const* d_in, const int* in_sizes, int n_in,
                              void* d_out, int out_size) {
    const int*   batch    = (const int*)d_in[0];
    const int*   x        = (const int*)d_in[1];
    const int*   ei       = (const int*)d_in[2];
    const int*   ea       = (const int*)d_in[3];
    const float* atom_emb = (const float*)d_in[4];
    const float* bond_emb = (const float*)d_in[5];
    const float* W1       = (const float*)d_in[6];
    const float* b1       = (const float*)d_in[7];
    const float* g1       = (const float*)d_in[8];
    const float* be1      = (const float*)d_in[9];
    const float* W2       = (const float*)d_in[10];
    const float* b2       = (const float*)d_in[11];
    const float* gbn      = (const float*)d_in[12];
    const float* bbn      = (const float*)d_in[13];
    float* out = (float*)d_out;

    float* g_h_p;   cudaGetSymbolAddress((void**)&g_h_p,  g_h);
    float* g_z1_p;  cudaGetSymbolAddress((void**)&g_z1_p, g_z1);
    float* g_z2_p;  cudaGetSymbolAddress((void**)&g_z2_p, g_z2);
    __nv_bfloat16 *Ahi_p, *Alo_p, *W1h_p, *W1l_p, *W2h_p, *W2l_p;
    cudaGetSymbolAddress((void**)&Ahi_p, g_Ahi);
    cudaGetSymbolAddress((void**)&Alo_p, g_Alo);
    cudaGetSymbolAddress((void**)&W1h_p, g_W1t_hi);
    cudaGetSymbolAddress((void**)&W1l_p, g_W1t_lo);
    cudaGetSymbolAddress((void**)&W2h_p, g_W2t_hi);
    cudaGetSymbolAddress((void**)&W2l_p, g_W2t_lo);

    // encoders
    encode_nodes<<<N_NODES, EMB>>>(x, atom_emb);
    encode_edges<<<N_EDGES, EMB>>>(ea, bond_emb);

    // CSR build
    zero_deg<<<(N_NODES + 255) / 256, 256>>>();
    count_deg<<<(N_EDGES + 255) / 256, 256>>>(ei);
    scan_deg<<<1, 1024>>>();
    fill_csr<<<(N_EDGES + 255) / 256, 256>>>(ei);

    // weight transpose + bf16 split (once per launch)
    {
        dim3 g1d(EMB2 / 32, EMB / 32, NLAYER);
        wsplit<<<g1d, dim3(32, 8)>>>(W1, W1h_p, W1l_p, EMB, EMB2);
        dim3 g2d(EMB / 32, EMB2 / 32, NLAYER);
        wsplit<<<g2d, dim3(32, 8)>>>(W2, W2h_p, W2l_p, EMB2, EMB);
    }

    const int MT = (N_NODES + 127) / 128;  // 391
    const int ROWCHUNK = 500;

    for (int l = 0; l < NLAYER; l++) {
        aggregate<<<N_NODES, 128>>>();

        gemm_mma<<<dim3(EMB2 / 128, MT), 256>>>(
            Ahi_p, Alo_p,
            W1h_p + (size_t)l * EMB2 * EMB, W1l_p + (size_t)l * EMB2 * EMB,
            b1 + l * EMB2, g_z2_p, N_NODES, EMB2, EMB);

        zero_stats<<<(EMB2 + 255) / 256, 256>>>();
        colstats<<<dim3(EMB2 / 128, (N_NODES + ROWCHUNK - 1) / ROWCHUNK), 128>>>(
            g_z2_p, EMB2, ROWCHUNK);
        bn_finalize<<<(EMB2 + 255) / 256, 256>>>(g1 + l * EMB2, be1 + l * EMB2, EMB2);
        bnrelu_split<<<N_NODES, EMB2>>>(g_z2_p, Ahi_p, Alo_p);

        gemm_mma<<<dim3(EMB / 128, MT), 256>>>(
            Ahi_p, Alo_p,
            W2h_p + (size_t)l * EMB * EMB2, W2l_p + (size_t)l * EMB * EMB2,
            b2 + l * EMB, g_z1_p, N_NODES, EMB, EMB2);

        zero_stats<<<(EMB2 + 255) / 256, 256>>>();
        colstats<<<dim3(EMB / 128, (N_NODES + ROWCHUNK - 1) / ROWCHUNK), 128>>>(
            g_z1_p, EMB, ROWCHUNK);
        bn_finalize<<<(EMB + 255) / 256, 256>>>(gbn + l * EMB, bbn + l * EMB, EMB);
        bnrelu_out<<<N_NODES, EMB>>>(g_z1_p, g_h_p,
                                     (l == NLAYER - 1) ? (out + GOFF) : nullptr);
    }

    boundaries_kernel<<<1, 128>>>(batch);
    pool<<<NUM_GRAPHS, 128>>>(g_h_p, out);
}

// round 4
// speedup vs baseline: 1.7609x; 1.1873x over previous
#include <cuda_runtime.h>
#include <cuda_bf16.h>
#include <cstdint>

#define N_NODES 50000
#define N_EDGES 400000
#define EMB 384
#define EMB2 768
#define NLAYER 5
#define NUM_GRAPHS 128
#define BN_EPS 1e-5f
#define GOFF (NUM_GRAPHS * EMB)

// ---------------- scratch (device globals) ----------------------------------
__device__ float g_h [N_NODES * EMB];
__device__ float g_z2[N_NODES * EMB2];   // GEMM1 output
__device__ float g_z1[N_NODES * EMB];    // GEMM2 output
__device__ __nv_bfloat16 g_Ahi[N_NODES * EMB2];
__device__ __nv_bfloat16 g_Alo[N_NODES * EMB2];
__device__ __nv_bfloat16 g_W1t_hi[NLAYER * EMB2 * EMB];
__device__ __nv_bfloat16 g_W1t_lo[NLAYER * EMB2 * EMB];
__device__ __nv_bfloat16 g_W2t_hi[NLAYER * EMB * EMB2];
__device__ __nv_bfloat16 g_W2t_lo[NLAYER * EMB * EMB2];
__device__ int   g_deg[N_NODES];
__device__ int   g_rowptr[N_NODES + 1];
__device__ int   g_cursor[N_NODES];
__device__ int   g_csr_src[N_EDGES];
__device__ int   g_csr_eid[N_EDGES];
__device__ float g_sum[EMB2];
__device__ float g_sumsq[EMB2];
__device__ float g_scale[EMB2];
__device__ float g_shift[EMB2];
__device__ int   g_gstart[NUM_GRAPHS + 1];

// ---------------- PTX helpers (sm_80-level only) -----------------------------
__device__ __forceinline__ uint32_t smem_u32(const void* p) {
    uint32_t a;
    asm("{ .reg .u64 t; cvta.to.shared.u64 t, %1; cvt.u32.u64 %0, t; }" : "=r"(a) : "l"(p));
    return a;
}
__device__ __forceinline__ void cp16(uint32_t dst, const void* src, int valid) {
    asm volatile("cp.async.ca.shared.global [%0], [%1], 16, %2;"
                 :: "r"(dst), "l"(src), "r"(valid ? 16 : 0));
}
__device__ __forceinline__ void cp_commit() {
    asm volatile("cp.async.commit_group;" ::: "memory");
}
__device__ __forceinline__ void cp_wait2() {
    asm volatile("cp.async.wait_group 2;" ::: "memory");
}
__device__ __forceinline__ void ldsm_x4(uint32_t& r0, uint32_t& r1, uint32_t& r2,
                                        uint32_t& r3, uint32_t addr) {
    asm volatile("ldmatrix.sync.aligned.m8n8.x4.shared.b16 {%0,%1,%2,%3}, [%4];"
                 : "=r"(r0), "=r"(r1), "=r"(r2), "=r"(r3) : "r"(addr));
}
__device__ __forceinline__ void mma16816(float* d, const uint32_t* a, const uint32_t* b) {
    asm volatile(
        "mma.sync.aligned.m16n8k16.row.col.f32.bf16.bf16.f32 "
        "{%0,%1,%2,%3}, {%4,%5,%6,%7}, {%8,%9}, {%0,%1,%2,%3};"
        : "+f"(d[0]), "+f"(d[1]), "+f"(d[2]), "+f"(d[3])
        : "r"(a[0]), "r"(a[1]), "r"(a[2]), "r"(a[3]), "r"(b[0]), "r"(b[1]));
}

// ---------------- encoders ---------------------------------------------------
__global__ void encode_nodes(const int* __restrict__ x,
                             const float* __restrict__ atom_emb) {
    int n = blockIdx.x, c = threadIdx.x;
    __shared__ int xs[9];
    if (c < 9) xs[c] = x[n * 9 + c];
    __syncthreads();
    float s = 0.f;
#pragma unroll
    for (int k = 0; k < 9; k++) s += atom_emb[((k << 6) + xs[k]) * EMB + c];
    g_h[(size_t)n * EMB + c] = s;
}

// ---------------- CSR build --------------------------------------------------
__global__ void zero_deg() {
    int i = blockIdx.x * blockDim.x + threadIdx.x;
    if (i < N_NODES) g_deg[i] = 0;
}
__global__ void count_deg(const int* __restrict__ ei) {
    int e = blockIdx.x * blockDim.x + threadIdx.x;
    if (e < N_EDGES) atomicAdd(&g_deg[ei[N_EDGES + e]], 1);
}
__global__ void scan_deg() {
    __shared__ int part[1024];
    const int T = 1024;
    int tid = threadIdx.x;
    const int per = (N_NODES + T - 1) / T;
    int start = tid * per;
    int end = start + per; if (end > N_NODES) end = N_NODES;
    if (start > N_NODES) start = N_NODES;
    int s = 0;
    for (int i = start; i < end; i++) s += g_deg[i];
    part[tid] = s;
    __syncthreads();
    for (int off = 1; off < T; off <<= 1) {
        int v = (tid >= off) ? part[tid - off] : 0;
        __syncthreads();
        part[tid] += v;
        __syncthreads();
    }
    int run = (tid == 0) ? 0 : part[tid - 1];
    for (int i = start; i < end; i++) {
        g_rowptr[i] = run; g_cursor[i] = run; run += g_deg[i];
    }
    if (tid == T - 1) g_rowptr[N_NODES] = run;
}
__global__ void fill_csr(const int* __restrict__ ei) {
    int e = blockIdx.x * blockDim.x + threadIdx.x;
    if (e >= N_EDGES) return;
    int dst = ei[N_EDGES + e];
    int pos = atomicAdd(&g_cursor[dst], 1);
    g_csr_src[pos] = ei[e];
    g_csr_eid[pos] = e;
}

// -------- aggregation: out = split(h + sum relu(h[src] + e_onthefly)) --------
// e recomputed from edge_attr + bond_emb table (36KB, L1-resident): no g_e.
__global__ void aggregate(const int* __restrict__ ea,
                          const float* __restrict__ bond_emb) {
    int n = blockIdx.x, t = threadIdx.x;   // 128 threads, 3 cols each
    const float* hr0 = g_h + (size_t)n * EMB;
    float a0 = hr0[t], a1 = hr0[t + 128], a2 = hr0[t + 256];
    int p0 = g_rowptr[n], p1 = g_rowptr[n + 1];
    for (int p = p0; p < p1; p++) {
        int s = g_csr_src[p], id = g_csr_eid[p];
        int e0 = __ldg(&ea[id * 3 + 0]);
        int e1 = __ldg(&ea[id * 3 + 1]);
        int e2 = __ldg(&ea[id * 3 + 2]);
        const float* T0 = bond_emb + (size_t)e0 * EMB;
        const float* T1 = bond_emb + (size_t)(8 + e1) * EMB;
        const float* T2 = bond_emb + (size_t)(16 + e2) * EMB;
        const float* hs = g_h + (size_t)s * EMB;
        a0 += fmaxf(hs[t]       + T0[t]       + T1[t]       + T2[t],       0.f);
        a1 += fmaxf(hs[t + 128] + T0[t + 128] + T1[t + 128] + T2[t + 128], 0.f);
        a2 += fmaxf(hs[t + 256] + T0[t + 256] + T1[t + 256] + T2[t + 256], 0.f);
    }
    size_t base = (size_t)n * EMB;
    float v[3] = {a0, a1, a2};
#pragma unroll
    for (int j = 0; j < 3; j++) {
        __nv_bfloat16 hi = __float2bfloat16(v[j]);
        g_Ahi[base + t + j * 128] = hi;
        g_Alo[base + t + j * 128] = __float2bfloat16(v[j] - __bfloat162float(hi));
    }
}

// ---------------- weight transpose + split (W[L][K][N] -> Wt[L][N][K]) ------
__global__ void wsplit(const float* __restrict__ W, __nv_bfloat16* __restrict__ Thi,
                       __nv_bfloat16* __restrict__ Tlo, int K, int N) {
    __shared__ float t[32][33];
    int l = blockIdx.z;
    int n0 = blockIdx.x * 32, k0 = blockIdx.y * 32;
    const float* Wl = W + (size_t)l * K * N;
    for (int i = threadIdx.y; i < 32; i += 8)
        t[i][threadIdx.x] = Wl[(size_t)(k0 + i) * N + n0 + threadIdx.x];
    __syncthreads();
    __nv_bfloat16* Hl = Thi + (size_t)l * K * N;
    __nv_bfloat16* Ll = Tlo + (size_t)l * K * N;
    for (int i = threadIdx.y; i < 32; i += 8) {
        float v = t[threadIdx.x][i];
        __nv_bfloat16 hi = __float2bfloat16(v);
        Hl[(size_t)(n0 + i) * K + k0 + threadIdx.x] = hi;
        Ll[(size_t)(n0 + i) * K + k0 + threadIdx.x] =
            __float2bfloat16(v - __bfloat162float(hi));
    }
}

// ---------------- HMMA bf16 split GEMM + fused BN column stats --------------
// C[M,Ntot] = (Ahi+Alo)[M,K] @ (Whi+Wlo)[Ntot,K]^T + bias  (3-term split)
// 128x128 tile, 8 warps (64x32 each), BK=32, 3-stage cp.async pipeline.
// Also accumulates per-column sum / sumsq of C into g_sum / g_sumsq.
#define BK 32
#define LDS_E 40                      // padded row stride (elements)
#define TILE_B (128 * LDS_E * 2)      // bytes per operand stage: 10240
#define STAGE_B (2 * TILE_B)          // A+B per stage: 20480
#define GEMM_SMEM (3 * STAGE_B)       // 61440
__global__ __launch_bounds__(256)
void gemm_mma(const __nv_bfloat16* __restrict__ Ahi,
              const __nv_bfloat16* __restrict__ Alo,
              const __nv_bfloat16* __restrict__ Whi,
              const __nv_bfloat16* __restrict__ Wlo,
              const float* __restrict__ bias,
              float* __restrict__ C,
              int M, int Ntot, int K) {
    extern __shared__ __align__(16) char smem[];   // 3 stages
    __shared__ float s_sum[128];
    __shared__ float s_sq[128];
    uint32_t sb = smem_u32(smem);
    const int CPS = K / BK;
    const int NC  = 3 * CPS;
    int tid = threadIdx.x, wid = tid >> 5, lane = tid & 31;
    int r0 = blockIdx.y * 128;
    int n0 = blockIdx.x * 128;
    int wm = (wid & 1) * 64;
    int wn = (wid >> 1) * 32;

    if (tid < 128) { s_sum[tid] = 0.f; s_sq[tid] = 0.f; }

    int ldr = tid >> 1;
    int ldc = (tid & 1) * 2;

    auto prefetch = [&](int c, int stage) {
        int seg = c / CPS;
        int kc = (c - seg * CPS) * BK;
        const __nv_bfloat16* Ap = (seg == 1) ? Alo : Ahi;
        const __nv_bfloat16* Bp = (seg == 2) ? Wlo : Whi;
        uint32_t abase = sb + stage * STAGE_B;
        uint32_t bbase = abase + TILE_B;
        int ar = r0 + ldr;
        int av = ar < M;
        const __nv_bfloat16* asrc = Ap + (size_t)ar * K + kc + ldc * 8;
        uint32_t adst = abase + (ldr * LDS_E + ldc * 8) * 2;
        cp16(adst,      asrc,     av);
        cp16(adst + 16, asrc + 8, av);
        const __nv_bfloat16* bsrc = Bp + (size_t)(n0 + ldr) * K + kc + ldc * 8;
        uint32_t bdst = bbase + (ldr * LDS_E + ldc * 8) * 2;
        cp16(bdst,      bsrc,     1);
        cp16(bdst + 16, bsrc + 8, 1);
    };

    float acc[4][4][4];
#pragma unroll
    for (int i = 0; i < 4; i++)
#pragma unroll
        for (int j = 0; j < 4; j++)
#pragma unroll
            for (int q = 0; q < 4; q++) acc[i][j][q] = 0.f;

    prefetch(0, 0); cp_commit();
    prefetch(1, 1); cp_commit();

    int cs = 0, ps = 2;
    for (int c = 0; c < NC; c++) {
        if (c + 2 < NC) prefetch(c + 2, ps);
        cp_commit();
        cp_wait2();
        __syncthreads();

        uint32_t abase = sb + cs * STAGE_B;
        uint32_t bbase = abase + TILE_B;
#pragma unroll
        for (int ks = 0; ks < 2; ks++) {
            int k0 = ks * 16;
            uint32_t af[4][4];
#pragma unroll
            for (int i = 0; i < 4; i++) {
                uint32_t addr = abase +
                    ((wm + i * 16 + (lane & 15)) * LDS_E + k0 + (lane >> 4) * 8) * 2;
                ldsm_x4(af[i][0], af[i][1], af[i][2], af[i][3], addr);
            }
            uint32_t bf[2][4];
#pragma unroll
            for (int p = 0; p < 2; p++) {
                uint32_t addr = bbase +
                    ((wn + p * 16 + (lane & 7) + ((lane >> 4) & 1) * 8) * LDS_E
                     + k0 + ((lane >> 3) & 1) * 8) * 2;
                ldsm_x4(bf[p][0], bf[p][1], bf[p][2], bf[p][3], addr);
            }
#pragma unroll
            for (int i = 0; i < 4; i++)
#pragma unroll
                for (int j = 0; j < 4; j++) {
                    uint32_t bb[2] = { bf[j >> 1][(j & 1) * 2],
                                       bf[j >> 1][(j & 1) * 2 + 1] };
                    mma16816(acc[i][j], af[i], bb);
                }
        }
        __syncthreads();
        cs = (cs == 2) ? 0 : cs + 1;
        ps = (ps == 2) ? 0 : ps + 1;
    }

    // epilogue: bias add + store + per-column stats (sum, sumsq)
#pragma unroll
    for (int j = 0; j < 4; j++) {
        int cloc = wn + j * 8 + (lane & 3) * 2;   // column within tile
        int col = n0 + cloc;
        float bx = bias[col], by = bias[col + 1];
        float s0 = 0.f, s1 = 0.f, q0 = 0.f, q1 = 0.f;
#pragma unroll
        for (int i = 0; i < 4; i++) {
            int ra = r0 + wm + i * 16 + (lane >> 2);
            int rb = ra + 8;
            if (ra < M) {
                float v0 = acc[i][j][0] + bx, v1 = acc[i][j][1] + by;
                *(float2*)(C + (size_t)ra * Ntot + col) = make_float2(v0, v1);
                s0 += v0; q0 += v0 * v0; s1 += v1; q1 += v1 * v1;
            }
            if (rb < M) {
                float v2 = acc[i][j][2] + bx, v3 = acc[i][j][3] + by;
                *(float2*)(C + (size_t)rb * Ntot + col) = make_float2(v2, v3);
                s0 += v2; q0 += v2 * v2; s1 += v3; q1 += v3 * v3;
            }
        }
#pragma unroll
        for (int off = 4; off <= 16; off <<= 1) {
            s0 += __shfl_xor_sync(0xFFFFFFFFu, s0, off);
            s1 += __shfl_xor_sync(0xFFFFFFFFu, s1, off);
            q0 += __shfl_xor_sync(0xFFFFFFFFu, q0, off);
            q1 += __shfl_xor_sync(0xFFFFFFFFu, q1, off);
        }
        if (lane < 4) {
            atomicAdd(&s_sum[cloc],     s0);
            atomicAdd(&s_sum[cloc + 1], s1);
            atomicAdd(&s_sq[cloc],      q0);
            atomicAdd(&s_sq[cloc + 1],  q1);
        }
    }
    __syncthreads();
    if (tid < 128) {
        atomicAdd(&g_sum[n0 + tid],   s_sum[tid]);
        atomicAdd(&g_sumsq[n0 + tid], s_sq[tid]);
    }
}

// ---------------- BatchNorm (training mode) ----------------------------------
__global__ void zero_stats() {
    int c = blockIdx.x * blockDim.x + threadIdx.x;
    if (c < EMB2) { g_sum[c] = 0.f; g_sumsq[c] = 0.f; }
}
__global__ void bn_finalize(const float* __restrict__ gamma,
                            const float* __restrict__ beta, int C) {
    int c = blockIdx.x * blockDim.x + threadIdx.x;
    if (c >= C) return;
    float m = g_sum[c] * (1.f / N_NODES);
    float v = g_sumsq[c] * (1.f / N_NODES) - m * m;
    float inv = rsqrtf(v + BN_EPS);
    float sc = gamma[c] * inv;
    g_scale[c] = sc;
    g_shift[c] = beta[c] - sc * m;
}

__global__ void bnrelu_split(const float* __restrict__ Z,
                             __nv_bfloat16* __restrict__ Hi,
                             __nv_bfloat16* __restrict__ Lo) {
    int c = threadIdx.x;
    size_t i = (size_t)blockIdx.x * blockDim.x + c;
    float v = fmaxf(g_scale[c] * Z[i] + g_shift[c], 0.f);
    __nv_bfloat16 hi = __float2bfloat16(v);
    Hi[i] = hi;
    Lo[i] = __float2bfloat16(v - __bfloat162float(hi));
}

__global__ void bnrelu_out(const float* __restrict__ Z, float* __restrict__ O1,
                           float* __restrict__ O2) {
    int c = threadIdx.x;
    size_t i = (size_t)blockIdx.x * blockDim.x + c;
    float v = fmaxf(g_scale[c] * Z[i] + g_shift[c], 0.f);
    O1[i] = v;
    if (O2) O2[i] = v;
}

// ---------------- pooling -----------------------------------------------------
__global__ void boundaries_kernel(const int* __restrict__ batch) {
    int g = threadIdx.x;
    if (g < NUM_GRAPHS) {
        int lo = 0, hi = N_NODES;
        while (lo < hi) {
            int mid = (lo + hi) >> 1;
            if (batch[mid] < g) lo = mid + 1; else hi = mid;
        }
        g_gstart[g] = lo;
    }
    if (g == 0) g_gstart[NUM_GRAPHS] = N_NODES;
}
__global__ void pool(const float* __restrict__ h, float* __restrict__ out) {
    int g = blockIdx.x, t = threadIdx.x;
    int s = g_gstart[g], e = g_gstart[g + 1];
    float a0 = 0.f, a1 = 0.f, a2 = 0.f;
    for (int r = s; r < e; r++) {
        const float* hr = h + (size_t)r * EMB;
        a0 += hr[t]; a1 += hr[t + 128]; a2 += hr[t + 256];
    }
    float* o = out + (size_t)g * EMB;
    o[t] = a0; o[t + 128] = a1; o[t + 256] = a2;
}

// ---------------- launch --------------------------------------------------------
extern "C" void kernel_launch(void* const* d_in, const int* in_sizes, int n_in,
                              void* d_out, int out_size) {
    const int*   batch    = (const int*)d_in[0];
    const int*   x        = (const int*)d_in[1];
    const int*   ei       = (const int*)d_in[2];
    const int*   ea       = (const int*)d_in[3];
    const float* atom_emb = (const float*)d_in[4];
    const float* bond_emb = (const float*)d_in[5];
    const float* W1       = (const float*)d_in[6];
    const float* b1       = (const float*)d_in[7];
    const float* g1       = (const float*)d_in[8];
    const float* be1      = (const float*)d_in[9];
    const float* W2       = (const float*)d_in[10];
    const float* b2       = (const float*)d_in[11];
    const float* gbn      = (const float*)d_in[12];
    const float* bbn      = (const float*)d_in[13];
    float* out = (float*)d_out;

    float* g_h_p;   cudaGetSymbolAddress((void**)&g_h_p,  g_h);
    float* g_z1_p;  cudaGetSymbolAddress((void**)&g_z1_p, g_z1);
    float* g_z2_p;  cudaGetSymbolAddress((void**)&g_z2_p, g_z2);
    __nv_bfloat16 *Ahi_p, *Alo_p, *W1h_p, *W1l_p, *W2h_p, *W2l_p;
    cudaGetSymbolAddress((void**)&Ahi_p, g_Ahi);
    cudaGetSymbolAddress((void**)&Alo_p, g_Alo);
    cudaGetSymbolAddress((void**)&W1h_p, g_W1t_hi);
    cudaGetSymbolAddress((void**)&W1l_p, g_W1t_lo);
    cudaGetSymbolAddress((void**)&W2h_p, g_W2t_hi);
    cudaGetSymbolAddress((void**)&W2l_p, g_W2t_lo);

    cudaFuncSetAttribute(gemm_mma, cudaFuncAttributeMaxDynamicSharedMemorySize,
                         GEMM_SMEM);

    // encoders (node only; edge features recomputed on the fly)
    encode_nodes<<<N_NODES, EMB>>>(x, atom_emb);

    // CSR build
    zero_deg<<<(N_NODES + 255) / 256, 256>>>();
    count_deg<<<(N_EDGES + 255) / 256, 256>>>(ei);
    scan_deg<<<1, 1024>>>();
    fill_csr<<<(N_EDGES + 255) / 256, 256>>>(ei);

    // weight transpose + bf16 split (once per launch)
    {
        dim3 g1d(EMB2 / 32, EMB / 32, NLAYER);
        wsplit<<<g1d, dim3(32, 8)>>>(W1, W1h_p, W1l_p, EMB, EMB2);
        dim3 g2d(EMB / 32, EMB2 / 32, NLAYER);
        wsplit<<<g2d, dim3(32, 8)>>>(W2, W2h_p, W2l_p, EMB2, EMB);
    }

    const int MT = (N_NODES + 127) / 128;  // 391

    for (int l = 0; l < NLAYER; l++) {
        aggregate<<<N_NODES, 128>>>(ea, bond_emb);

        zero_stats<<<(EMB2 + 255) / 256, 256>>>();
        gemm_mma<<<dim3(EMB2 / 128, MT), 256, GEMM_SMEM>>>(
            Ahi_p, Alo_p,
            W1h_p + (size_t)l * EMB2 * EMB, W1l_p + (size_t)l * EMB2 * EMB,
            b1 + l * EMB2, g_z2_p, N_NODES, EMB2, EMB);
        bn_finalize<<<(EMB2 + 255) / 256, 256>>>(g1 + l * EMB2, be1 + l * EMB2, EMB2);
        bnrelu_split<<<N_NODES, EMB2>>>(g_z2_p, Ahi_p, Alo_p);

        zero_stats<<<(EMB2 + 255) / 256, 256>>>();
        gemm_mma<<<dim3(EMB / 128, MT), 256, GEMM_SMEM>>>(
            Ahi_p, Alo_p,
            W2h_p + (size_t)l * EMB * EMB2, W2l_p + (size_t)l * EMB * EMB2,
            b2 + l * EMB, g_z1_p, N_NODES, EMB, EMB2);
        bn_finalize<<<(EMB + 255) / 256, 256>>>(gbn + l * EMB, bbn + l * EMB, EMB);
        bnrelu_out<<<N_NODES, EMB>>>(g_z1_p, g_h_p,
                                     (l == NLAYER - 1) ? (out + GOFF) : nullptr);
    }

    boundaries_kernel<<<1, 128>>>(batch);
    pool<<<NUM_GRAPHS, 128>>>(g_h_p, out);
}